// round 7
// baseline (speedup 1.0000x reference)
#include <cuda_runtime.h>
#include <math.h>

// Problem: B=64, V=8, J=17, H=256
// keypoints_gt: (B,V,J,2) float32   -> d_in[0], 17408 elems
// heatmap:      (B,V,1,H,H) float32 -> d_in[1], 33554432 elems
// out: scalar float = mean over B*V*J of -log(hm[b,v, clip(ceil(ky)), clip(ceil(kx))])

#define NTOT   8704      // 64*8*17
#define JDIM   17
#define HDIM   256
#define NBLK   136       // 136 * 32 * 2 = 8704; one warp per block, 2 elems/thread
#define NTHR   32
#define HALF   4352      // NTOT / 2
#define NPART  136       // one partial per warp = 34 float4

// Partials double as completion flags: -log(val) > 0 strictly, so a finished
// partial can never be bit-pattern zero. Zero-initialized at module load;
// poller resets to zero each call for graph replays.
__device__ float g_partials[NPART];   // zero-init

__device__ __forceinline__ float4 ld_relaxed_v4(const float4* p) {
    float4 v;
    asm volatile("ld.relaxed.gpu.global.v4.f32 {%0,%1,%2,%3}, [%4];"
                 : "=f"(v.x), "=f"(v.y), "=f"(v.z), "=f"(v.w)
                 : "l"(p) : "memory");
    return v;
}
__device__ __forceinline__ void st_relaxed(float* p, float v) {
    asm volatile("st.relaxed.gpu.global.f32 [%0], %1;" :: "l"(p), "f"(v) : "memory");
}

__device__ __forceinline__ long long gather_off(float2 k, int i) {
    int xi = (int)ceilf(k.x);
    int yi = (int)ceilf(k.y);
    xi = min(max(xi, 0), HDIM - 1);
    yi = min(max(yi, 0), HDIM - 1);
    const int bv = i / JDIM;                          // (b*V + v)
    return (long long)bv * (HDIM * HDIM) + yi * HDIM + xi;
}

__global__ __launch_bounds__(NTHR) void heatmap_ce_fused_kernel(
    const float* __restrict__ kp,   // (NTOT, 2)
    const float* __restrict__ hm,   // (B*V, H, H)
    float* __restrict__ out)
{
    const int lane = threadIdx.x;                     // block == warp
    const int i0 = blockIdx.x * NTHR + lane;          // 0..4351
    const int i1 = i0 + HALF;                         // 4352..8703

    // two coalesced float2 keypoint loads, issued back-to-back (MLP=2)
    const float2 k0 = reinterpret_cast<const float2*>(kp)[i0];
    const float2 k1 = reinterpret_cast<const float2*>(kp)[i1];

    const long long off0 = gather_off(k0, i0);
    const long long off1 = gather_off(k1, i1);

    // both gathers issued before either is consumed (MLP=2)
    const float v0 = __ldg(&hm[off0]);
    const float v1 = __ldg(&hm[off1]);

    float s = -__logf(v0) - __logf(v1);   // strictly > 0; fast log within 1e-3 tol

    // warp reduce (5 shfl levels) — no smem, no __syncthreads
    #pragma unroll
    for (int o = 16; o > 0; o >>= 1)
        s += __shfl_down_sync(0xFFFFFFFFu, s, o);

    if (lane == 0)
        st_relaxed(&g_partials[blockIdx.x], s);       // value IS the flag

    // Fixed poller: block 0's warp. 136 partials = 34 float4.
    // lane owns float4 index lane; lanes 0,1 also own lane+32.
    if (blockIdx.x == 0) {
        const float4* p4 = reinterpret_cast<const float4*>(g_partials);
        float4 a, b;
        bool da = false, db = (lane >= 34 - 32);
        b = make_float4(0.f, 0.f, 0.f, 0.f);
        while (true) {
            if (!da) { a = ld_relaxed_v4(&p4[lane]);
                       da = (a.x != 0.f) & (a.y != 0.f) & (a.z != 0.f) & (a.w != 0.f); }
            if (!db) { b = ld_relaxed_v4(&p4[lane + 32]);
                       db = (b.x != 0.f) & (b.y != 0.f) & (b.z != 0.f) & (b.w != 0.f); }
            if (__all_sync(0xFFFFFFFFu, da && db)) break;
        }

        // fixed-order summation (deterministic)
        float s2 = ((a.x + a.y) + (a.z + a.w))
                 + ((b.x + b.y) + (b.z + b.w));
        #pragma unroll
        for (int o = 16; o > 0; o >>= 1)
            s2 += __shfl_down_sync(0xFFFFFFFFu, s2, o);

        if (lane == 0)
            out[0] = s2 * (1.0f / (float)NTOT);

        // rearm sentinels for the next graph replay
        float4* q4 = reinterpret_cast<float4*>(g_partials);
        const float4 z = make_float4(0.f, 0.f, 0.f, 0.f);
        q4[lane] = z;
        if (lane < 34 - 32) q4[lane + 32] = z;
    }
}

extern "C" void kernel_launch(void* const* d_in, const int* in_sizes, int n_in,
                              void* d_out, int out_size)
{
    const float* kp = (const float*)d_in[0];
    const float* hm = (const float*)d_in[1];
    float* out = (float*)d_out;

    heatmap_ce_fused_kernel<<<NBLK, NTHR>>>(kp, hm, out);
}

// round 8
// speedup vs baseline: 1.0435x; 1.0435x over previous
#include <cuda_runtime.h>
#include <math.h>

// Problem: B=64, V=8, J=17, H=256
// keypoints_gt: (B,V,J,2) float32   -> d_in[0], 17408 elems
// heatmap:      (B,V,1,H,H) float32 -> d_in[1], 33554432 elems
// out: scalar float = mean over B*V*J of -log(hm[b,v, clip(ceil(ky)), clip(ceil(kx))])

#define NTOT   8704      // 64*8*17
#define JDIM   17
#define HDIM   256
#define NBLK   272       // 272 * 32 = 8704 exactly; one warp per block
#define NTHR   32

// Partials double as completion flags: -log(val) > 0 strictly, so a finished
// partial can never be bit-pattern zero. Zero-initialized at module load;
// poller resets to zero each call for graph replays.
__device__ float g_partials[NBLK];   // zero-init

__device__ __forceinline__ float4 ld_relaxed_v4(const float4* p) {
    float4 v;
    asm volatile("ld.relaxed.gpu.global.v4.f32 {%0,%1,%2,%3}, [%4];"
                 : "=f"(v.x), "=f"(v.y), "=f"(v.z), "=f"(v.w)
                 : "l"(p) : "memory");
    return v;
}
__device__ __forceinline__ void st_relaxed(float* p, float v) {
    asm volatile("st.relaxed.gpu.global.f32 [%0], %1;" :: "l"(p), "f"(v) : "memory");
}

__global__ __launch_bounds__(NTHR) void heatmap_ce_fused_kernel(
    const float* __restrict__ kp,   // (NTOT, 2)
    const float* __restrict__ hm,   // (B*V, H, H)
    float* __restrict__ out)
{
    const int lane = threadIdx.x;                     // block == warp
    const int i = blockIdx.x * NTHR + lane;           // 0..8703, exact

    // coalesced float2 keypoint load
    const float2 k = reinterpret_cast<const float2*>(kp)[i];

    int xi = (int)ceilf(k.x);
    int yi = (int)ceilf(k.y);
    xi = min(max(xi, 0), HDIM - 1);
    yi = min(max(yi, 0), HDIM - 1);

    const int bv = i / JDIM;                          // (b*V + v)
    const long long off = (long long)bv * (HDIM * HDIM) + yi * HDIM + xi;

    const float val = __ldg(&hm[off]);
    float s = -__logf(val);    // strictly > 0; fast log well within 1e-3 tol

    // warp reduce (5 shfl levels) — no smem, no __syncthreads
    #pragma unroll
    for (int o = 16; o > 0; o >>= 1)
        s += __shfl_down_sync(0xFFFFFFFFu, s, o);

    if (lane == 0)
        st_relaxed(&g_partials[blockIdx.x], s);       // value IS the flag

    // Fixed poller: block 0's warp (first dispatched -> longest spin overlap).
    // 272 partials = 68 float4. lane owns f4 idx: lane, lane+32, lanes 0..3 lane+64.
    if (blockIdx.x == 0) {
        const float4* p4 = reinterpret_cast<const float4*>(g_partials);
        float4 a, b, c;
        bool da = false, db = false, dc = (lane >= 68 - 64);
        c = make_float4(0.f, 0.f, 0.f, 0.f);
        while (true) {
            if (!da) { a = ld_relaxed_v4(&p4[lane]);
                       da = (a.x != 0.f) & (a.y != 0.f) & (a.z != 0.f) & (a.w != 0.f); }
            if (!db) { b = ld_relaxed_v4(&p4[lane + 32]);
                       db = (b.x != 0.f) & (b.y != 0.f) & (b.z != 0.f) & (b.w != 0.f); }
            if (!dc) { c = ld_relaxed_v4(&p4[lane + 64]);
                       dc = (c.x != 0.f) & (c.y != 0.f) & (c.z != 0.f) & (c.w != 0.f); }
            if (__all_sync(0xFFFFFFFFu, da && db && dc)) break;
        }

        // Rearm sentinels NOW — values already live in registers; these STGs
        // overlap with the shfl-reduce dependency chain below.
        float4* q4 = reinterpret_cast<float4*>(g_partials);
        const float4 z = make_float4(0.f, 0.f, 0.f, 0.f);
        q4[lane]      = z;
        q4[lane + 32] = z;
        if (lane < 68 - 64) q4[lane + 64] = z;

        // fixed-order pairwise summation (deterministic)
        float s2 = ((a.x + a.y) + (a.z + a.w))
                 + (((b.x + b.y) + (b.z + b.w))
                 +  ((c.x + c.y) + (c.z + c.w)));
        #pragma unroll
        for (int o = 16; o > 0; o >>= 1)
            s2 += __shfl_down_sync(0xFFFFFFFFu, s2, o);

        if (lane == 0)
            out[0] = s2 * (1.0f / (float)NTOT);
    }
}

extern "C" void kernel_launch(void* const* d_in, const int* in_sizes, int n_in,
                              void* d_out, int out_size)
{
    const float* kp = (const float*)d_in[0];
    const float* hm = (const float*)d_in[1];
    float* out = (float*)d_out;

    heatmap_ce_fused_kernel<<<NBLK, NTHR>>>(kp, hm, out);
}